// round 10
// baseline (speedup 1.0000x reference)
#include <cuda_runtime.h>

// ST-BIF IF neuron, T=16 scan. R9 winner (8 elems/thread, 2x float4, block=64,
// __ldcs/__stcs) with S specialized as a compile-time constant so all 16
// timestep offsets fold into immediate address arithmetic. Generic fallback
// kernel handles any other S (deterministic dispatch on input size).

#define T_STEPS 16
#define POS_MAX 7.0f
#define NEG_MIN (-8.0f)
#define S_FIXED (64 * 196 * 768)   // 9,633,792

__device__ __forceinline__ void step_elem(float& v, float rcp, float qth,
                                          float& q, float& a)
{
    q += v * rcp;                    // qth = 0.5 -> rcp = 2.0 exact
    bool sp = (q - 1.0f >= 0.0f) && (a < POS_MAX);
    bool ng = (q < 0.0f) && (a > NEG_MIN);
    float cur = sp ? 1.0f : (ng ? -1.0f : 0.0f);
    a += cur;
    q -= cur;
    v = cur * qth;                   // output overwrites input register
}

template <int S_CONST>
__global__ void __launch_bounds__(64) ifneuron_body(
    const float* __restrict__ x,
    const float* __restrict__ qth_ptr,
    float* __restrict__ out,
    int S_dyn)
{
    const int S = (S_CONST > 0) ? S_CONST : S_dyn;

    int idx = (blockIdx.x * blockDim.x + threadIdx.x) * 8;
    if (idx >= S) return;

    const float qth = __ldg(qth_ptr);
    const float rcp = 1.0f / qth;

    float q[8];
    float a[8];
    #pragma unroll
    for (int i = 0; i < 8; i++) { q[i] = 0.5f; a[i] = 0.0f; }

    const float* xp = x + idx;
    float*       op = out + idx;

    #pragma unroll
    for (int t = 0; t < T_STEPS; t++) {
        float4 xa = __ldcs(reinterpret_cast<const float4*>(xp + (size_t)t * S));
        float4 xb = __ldcs(reinterpret_cast<const float4*>(xp + (size_t)t * S + 4));

        step_elem(xa.x, rcp, qth, q[0], a[0]);
        step_elem(xa.y, rcp, qth, q[1], a[1]);
        step_elem(xa.z, rcp, qth, q[2], a[2]);
        step_elem(xa.w, rcp, qth, q[3], a[3]);
        step_elem(xb.x, rcp, qth, q[4], a[4]);
        step_elem(xb.y, rcp, qth, q[5], a[5]);
        step_elem(xb.z, rcp, qth, q[6], a[6]);
        step_elem(xb.w, rcp, qth, q[7], a[7]);

        __stcs(reinterpret_cast<float4*>(op + (size_t)t * S), xa);
        __stcs(reinterpret_cast<float4*>(op + (size_t)t * S + 4), xb);
    }
}

extern "C" void kernel_launch(void* const* d_in, const int* in_sizes, int n_in,
                              void* d_out, int out_size)
{
    const float* x   = (const float*)d_in[0];
    const float* qth = (const float*)d_in[1];
    float* out       = (float*)d_out;

    int total = in_sizes[0];          // T * S
    int S = total / T_STEPS;
    int block = 64;
    int grid = (S / 8 + block - 1) / block;

    if (S == S_FIXED) {
        ifneuron_body<S_FIXED><<<grid, block>>>(x, qth, out, S);
    } else {
        ifneuron_body<0><<<grid, block>>>(x, qth, out, S);
    }
}

// round 11
// speedup vs baseline: 1.0224x; 1.0224x over previous
#include <cuda_runtime.h>

// ST-BIF IF neuron, T=16 scan — FINAL (R9 measured optimum, 184.26us,
// 6413 GB/s = 80.9% DRAM). 8 elems/thread (2x float4, MLP_p1=2), block=64,
// __ldcs/__stcs streaming, rcp-multiply (exact for qth=0.5), float acc with
// a single select chain. regs=50 self-limits occupancy to ~52% which R4/R10
// showed is the sweet spot (higher occ -> L1tex queue contention).

#define T_STEPS 16
#define POS_MAX 7.0f
#define NEG_MIN (-8.0f)

__device__ __forceinline__ void step_elem(float& v, float rcp, float qth,
                                          float& q, float& a)
{
    q += v * rcp;                    // qth = 0.5 -> rcp = 2.0 exact
    bool sp = (q - 1.0f >= 0.0f) && (a < POS_MAX);
    bool ng = (q < 0.0f) && (a > NEG_MIN);
    float cur = sp ? 1.0f : (ng ? -1.0f : 0.0f);
    a += cur;
    q -= cur;
    v = cur * qth;                   // output overwrites input register
}

__global__ void __launch_bounds__(64) ifneuron_kernel(
    const float* __restrict__ x,
    const float* __restrict__ qth_ptr,
    float* __restrict__ out,
    int S)   // spatial size (B*N*D), multiple of 8
{
    int idx = (blockIdx.x * blockDim.x + threadIdx.x) * 8;
    if (idx >= S) return;

    const float qth = __ldg(qth_ptr);
    const float rcp = 1.0f / qth;

    float q[8];
    float a[8];
    #pragma unroll
    for (int i = 0; i < 8; i++) { q[i] = 0.5f; a[i] = 0.0f; }

    #pragma unroll
    for (int t = 0; t < T_STEPS; t++) {
        const float* xp = x + (size_t)t * S + idx;
        float4 xa = __ldcs(reinterpret_cast<const float4*>(xp));
        float4 xb = __ldcs(reinterpret_cast<const float4*>(xp + 4));

        step_elem(xa.x, rcp, qth, q[0], a[0]);
        step_elem(xa.y, rcp, qth, q[1], a[1]);
        step_elem(xa.z, rcp, qth, q[2], a[2]);
        step_elem(xa.w, rcp, qth, q[3], a[3]);
        step_elem(xb.x, rcp, qth, q[4], a[4]);
        step_elem(xb.y, rcp, qth, q[5], a[5]);
        step_elem(xb.z, rcp, qth, q[6], a[6]);
        step_elem(xb.w, rcp, qth, q[7], a[7]);

        float* op = out + (size_t)t * S + idx;
        __stcs(reinterpret_cast<float4*>(op), xa);
        __stcs(reinterpret_cast<float4*>(op + 4), xb);
    }
}

extern "C" void kernel_launch(void* const* d_in, const int* in_sizes, int n_in,
                              void* d_out, int out_size)
{
    const float* x   = (const float*)d_in[0];
    const float* qth = (const float*)d_in[1];
    float* out       = (float*)d_out;

    int total = in_sizes[0];          // T * S
    int S = total / T_STEPS;          // 9,633,792
    int nthreads = S / 8;
    int block = 64;
    int grid = (nthreads + block - 1) / block;

    ifneuron_kernel<<<grid, block>>>(x, qth, out, S);
}